// round 1
// baseline (speedup 1.0000x reference)
#include <cuda_runtime.h>

#define TILE_W 32
#define TILE_H 4
#define KR 5
#define PADV 2
#define CCH 3
#define F 64
#define D 75          // CCH * KR * KR
#define HW 64
#define SX_W (TILE_W + 4)   // 36
#define SX_H (TILE_H + 4)   // 8

__global__ __launch_bounds__(128, 2)
void euclid2d_kernel(const float* __restrict__ x,
                     const float* __restrict__ W,
                     float* __restrict__ out) {
    __shared__ float sW[F * D];
    __shared__ float sw2[F];
    __shared__ float sx[CCH][SX_H][SX_W];

    const int tid = threadIdx.x;           // 0..127
    const int tx  = tid & (TILE_W - 1);    // 0..31
    const int ty  = tid / TILE_W;          // 0..3
    const int bx  = blockIdx.x;            // 0..1
    const int by  = blockIdx.y;            // 0..15
    const int n   = blockIdx.z;            // 0..7

    // ---- load W into smem (4800 floats, coalesced) ----
    for (int i = tid; i < F * D; i += 128) sW[i] = W[i];

    // ---- load x tile with halo (zero-padded) ----
    const int x0 = bx * TILE_W - PADV;
    const int y0 = by * TILE_H - PADV;
    for (int i = tid; i < CCH * SX_H * SX_W; i += 128) {
        int cc  = i / (SX_H * SX_W);
        int r   = (i / SX_W) % SX_H;
        int col = i % SX_W;
        int gy = y0 + r, gx = x0 + col;
        float v = 0.0f;
        if (gy >= 0 && gy < HW && gx >= 0 && gx < HW)
            v = x[((n * CCH + cc) * HW + gy) * HW + gx];
        sx[cc][r][col] = v;
    }
    __syncthreads();

    // ---- per-filter squared norms ----
    if (tid < F) {
        float s = 0.0f;
        #pragma unroll
        for (int d = 0; d < D; d++) {
            float w = sW[tid * D + d];
            s += w * w;
        }
        sw2[tid] = s;
    }
    __syncthreads();

    // ---- gather this thread's patch into registers ----
    float patch[D];
    #pragma unroll
    for (int c = 0; c < CCH; c++)
        #pragma unroll
        for (int kh = 0; kh < KR; kh++)
            #pragma unroll
            for (int kw = 0; kw < KR; kw++)
                patch[(c * KR + kh) * KR + kw] = sx[c][ty + kh][tx + kw];

    float x2 = 0.0f;
    #pragma unroll
    for (int d = 0; d < D; d++) x2 += patch[d] * patch[d];

    const int ho = by * TILE_H + ty;
    const int wo = bx * TILE_W + tx;
    float* op = out + ((long)(n * F) * HW + ho) * HW + wo;

    // ---- 64 filters, 4 independent FMA chains each ----
    #pragma unroll 2
    for (int f = 0; f < F; f++) {
        const float* wf = &sW[f * D];
        float a0 = 0.0f, a1 = 0.0f, a2 = 0.0f, a3 = 0.0f;
        #pragma unroll
        for (int d = 0; d < 72; d += 4) {
            a0 += wf[d + 0] * patch[d + 0];
            a1 += wf[d + 1] * patch[d + 1];
            a2 += wf[d + 2] * patch[d + 2];
            a3 += wf[d + 3] * patch[d + 3];
        }
        a0 += wf[72] * patch[72];
        a1 += wf[73] * patch[73];
        a2 += wf[74] * patch[74];
        float acc = (a0 + a1) + (a2 + a3);
        op[f * (HW * HW)] = acc - 0.5f * (x2 + sw2[f]);
    }
}

extern "C" void kernel_launch(void* const* d_in, const int* in_sizes, int n_in,
                              void* d_out, int out_size) {
    const float* x = (const float*)d_in[0];
    const float* W = (const float*)d_in[1];
    float* out = (float*)d_out;

    dim3 grid(HW / TILE_W, HW / TILE_H, 8);  // (2, 16, 8) = 256 CTAs
    dim3 block(TILE_W * TILE_H);             // 128 threads
    euclid2d_kernel<<<grid, block>>>(x, W, out);
}

// round 2
// speedup vs baseline: 1.0107x; 1.0107x over previous
#include <cuda_runtime.h>

#define KR   5
#define PADV 2
#define CCH  3
#define F    64
#define D    75          // CCH*KR*KR
#define HW   64
#define TW   32
#define TH   4
#define FG   16          // filters per CTA
#define NFG  (F / FG)    // 4 filter groups
#define SXW  (TW + 4)    // 36
#define SXH  (TH + 4)    // 8

typedef unsigned long long u64;

__global__ __launch_bounds__(128)
void euclid2d_kernel(const float* __restrict__ x,
                     const float* __restrict__ W,
                     float* __restrict__ out) {
    // patch tile stored as duplicated f32x2 pairs (v,v)
    __shared__ __align__(16) u64   sxp[CCH][SXH][SXW];
    // weights transposed: sWT[d][f] for this CTA's 16 filters (pairs contiguous)
    __shared__ __align__(16) float sWT[D][FG];
    __shared__ __align__(16) u64   sw2p[FG / 2];   // (w2_f0, w2_f1) pairs

    const int tid = threadIdx.x;          // 0..127
    const int tx  = tid & 31;             // 0..31
    const int ty  = tid >> 5;             // 0..3
    const int bx  = blockIdx.x & 1;       // tile x: 0..1
    const int fg  = blockIdx.x >> 1;      // filter group: 0..3
    const int by  = blockIdx.y;           // 0..15
    const int n   = blockIdx.z;           // 0..7
    const int fbase = fg * FG;

    // ---- load W (transposed) ----
    for (int i = tid; i < FG * D; i += 128) {
        int f = i / D, d = i % D;
        sWT[d][f] = W[(fbase + f) * D + d];
    }

    // ---- load x tile with halo, duplicate into (v,v) pairs ----
    const int x0 = bx * TW - PADV;
    const int y0 = by * TH - PADV;
    for (int i = tid; i < CCH * SXH * SXW; i += 128) {
        int c   = i / (SXH * SXW);
        int r   = (i / SXW) % SXH;
        int col = i % SXW;
        int gy = y0 + r, gx = x0 + col;
        float v = 0.0f;
        if (gy >= 0 && gy < HW && gx >= 0 && gx < HW)
            v = x[((n * CCH + c) * HW + gy) * HW + gx];
        u64 p;
        asm("mov.b64 %0, {%1, %1};" : "=l"(p) : "f"(v));
        sxp[c][r][col] = p;
    }
    __syncthreads();

    // ---- per-filter-pair squared norms ----
    if (tid < FG / 2) {
        float a = 0.f, b = 0.f;
        #pragma unroll
        for (int d = 0; d < D; d++) {
            float wa = sWT[d][2 * tid];
            float wb = sWT[d][2 * tid + 1];
            a += wa * wa;
            b += wb * wb;
        }
        u64 p;
        asm("mov.b64 %0, {%1, %2};" : "=l"(p) : "f"(a), "f"(b));
        sw2p[tid] = p;
    }
    __syncthreads();

    // ---- main loop: 8 filter-pair accumulators + packed x^2 chain ----
    u64 acc[FG / 2];
    #pragma unroll
    for (int j = 0; j < FG / 2; j++) acc[j] = 0ULL;
    u64 x2a = 0ULL;

    const u64* pbase = &sxp[0][ty][tx];

    #pragma unroll
    for (int c = 0; c < CCH; c++)
        #pragma unroll
        for (int kh = 0; kh < KR; kh++)
            #pragma unroll
            for (int kw = 0; kw < KR; kw++) {
                const int d = (c * KR + kh) * KR + kw;
                u64 pp = pbase[c * (SXH * SXW) + kh * SXW + kw];   // LDS.64
                asm("fma.rn.f32x2 %0, %1, %1, %0;" : "+l"(x2a) : "l"(pp));
                const ulonglong2* wr = (const ulonglong2*)&sWT[d][0];
                #pragma unroll
                for (int j = 0; j < 4; j++) {
                    ulonglong2 w2v = wr[j];                        // LDS.128 uniform
                    asm("fma.rn.f32x2 %0, %1, %2, %0;"
                        : "+l"(acc[2 * j])     : "l"(pp), "l"(w2v.x));
                    asm("fma.rn.f32x2 %0, %1, %2, %0;"
                        : "+l"(acc[2 * j + 1]) : "l"(pp), "l"(w2v.y));
                }
            }

    // ---- epilogue: out = dot - 0.5*(x2 + w2) ----
    const int ho = by * TH + ty;
    const int wo = bx * TW + tx;
    float* op = out + (((long)n * F + fbase) * HW + ho) * HW + wo;

    u64 nh;
    {
        float mh = -0.5f;
        asm("mov.b64 %0, {%1, %1};" : "=l"(nh) : "f"(mh));
    }

    #pragma unroll
    for (int j = 0; j < FG / 2; j++) {
        u64 t = acc[j];
        asm("fma.rn.f32x2 %0, %1, %2, %0;" : "+l"(t) : "l"(x2a),    "l"(nh));
        asm("fma.rn.f32x2 %0, %1, %2, %0;" : "+l"(t) : "l"(sw2p[j]), "l"(nh));
        float lo, hi;
        asm("mov.b64 {%0, %1}, %2;" : "=f"(lo), "=f"(hi) : "l"(t));
        op[(2 * j)     * (HW * HW)] = lo;
        op[(2 * j + 1) * (HW * HW)] = hi;
    }
}

extern "C" void kernel_launch(void* const* d_in, const int* in_sizes, int n_in,
                              void* d_out, int out_size) {
    const float* x = (const float*)d_in[0];
    const float* W = (const float*)d_in[1];
    float* out = (float*)d_out;

    dim3 grid(2 * NFG, HW / TH, 8);   // (8, 16, 8) = 1024 CTAs
    dim3 block(128);
    euclid2d_kernel<<<grid, block>>>(x, W, out);
}